// round 13
// baseline (speedup 1.0000x reference)
#include <cuda_runtime.h>
#include <cstdint>
#include <cstddef>

#define BB 128
#define NN 2048
#define HH 64
#define SS 64

typedef unsigned long long u64;

// ---------------- global scratch (static; no allocation) ----------------
__device__ __align__(256) float d_h0[(size_t)BB * HH * NN];   // 64 MB, [b][c][rank]
__device__ __align__(256) float d_h1[(size_t)BB * HH * NN];   // 64 MB
__device__ __align__(256) float d_agg0[BB * SS * HH];
__device__ __align__(256) float d_agg1[BB * SS * HH];
__device__ __align__(256) float d_agg2[BB * SS * HH];
__device__ __align__(256) float d_aggW[BB * SS * HH];
__device__ int            d_perm[BB * NN];
__device__ int            d_cs[BB * NN];
__device__ int            g_arr[8];   // zero-init; barrier resets them each launch
__device__ int            g_dep[8];

// ---------------- f32x2 packed fp32 helpers ----------------
__device__ __forceinline__ u64 pack2f(float lo, float hi) {
    u64 r; asm("mov.b64 %0, {%1,%2};" : "=l"(r) : "f"(lo), "f"(hi)); return r;
}
__device__ __forceinline__ void unpack2f(u64 v, float& lo, float& hi) {
    asm("mov.b64 {%0,%1}, %2;" : "=f"(lo), "=f"(hi) : "l"(v));
}
__device__ __forceinline__ u64 fma2f(u64 a, u64 b, u64 c) {
    u64 d; asm("fma.rn.f32x2 %0, %1, %2, %3;" : "=l"(d) : "l"(a), "l"(b), "l"(c)); return d;
}

// ---------------- cp.async (cg: bypass L1, cache L2 only — cross-phase safe) ----------------
__device__ __forceinline__ void cp_async_cg16(uint32_t dst_smem, const void* src) {
    asm volatile("cp.async.cg.shared.global [%0], [%1], 16;" :: "r"(dst_smem), "l"(src));
}
__device__ __forceinline__ void cp_commit() {
    asm volatile("cp.async.commit_group;" ::: "memory");
}
template <int N>
__device__ __forceinline__ void cp_wait() {
    asm volatile("cp.async.wait_group %0;" :: "n"(N) : "memory");
}

// ---------------- software global barrier (self-resetting per launch) ----------------
__device__ __forceinline__ void gbar(int k) {
    __syncthreads();
    __threadfence();
    if (threadIdx.x == 0) {
        int nb = gridDim.x;
        volatile int* va = g_arr + k;
        atomicAdd(&g_arr[k], 1);
        while (*va < nb) __nanosleep(64);
        int d = atomicAdd(&g_dep[k], 1) + 1;
        if (d == nb) { *va = 0; __threadfence(); *(volatile int*)(g_dep + k) = 0; }
    }
    __syncthreads();
}

// smem budget: wsm 16K + hsm 32K + gsm/besm 512B
#define FK_SMEM ((HH * HH + HH * 128 + 2 * HH) * 4)

// ---------------- smallmm phase: aggW = bias + agg @ W_bot ----------------
__device__ __forceinline__ void smallmm_phase(float* sm, const float* Wfull,
                                              const float* bias, const float* aggsrc) {
    float* Wsm = sm;
    float* bsm = sm + HH * HH;
    int tid = threadIdx.x;
    const float* Wbot = Wfull + 64 * HH;
    for (int i = tid; i < HH * HH; i += 128) Wsm[i] = Wbot[i];
    if (tid < HH) bsm[tid] = bias[tid];
    __syncthreads();
    int stride = gridDim.x * 128;
    for (int gid = blockIdx.x * 128 + tid; gid < BB * SS * HH; gid += stride) {
        int c = gid & 63;
        int row = gid >> 6;
        const float* A = aggsrc + (row << 6);
        float a = bsm[c];
#pragma unroll 8
        for (int k = 0; k < HH; k++) a = fmaf(__ldcg(A + k), Wsm[(k << 6) + c], a);
        __stcg(d_aggW + gid, a);
    }
}

// ---------------- layer12 phase: P=8 x C=8, whole-tile h in smem, grid-stride tiles ----
template <bool WRITE>
__device__ __forceinline__ void layer12_phase(float* sm, const float* W,
                                              const float* g, const float* be,
                                              const float* hin, float* hout, float* aggdst) {
    float* wsm  = sm;                 // 16 KB swizzled [k][slot]
    float* hsm  = sm + HH * HH;       // 32 KB [k][point]
    float* gsm  = hsm + HH * 128;
    float* besm = gsm + HH;
    int tid = threadIdx.x;
    int pg = tid >> 3, cg = tid & 7;
    uint32_t hsm_base = (uint32_t)__cvta_generic_to_shared(hsm);

    // stage W + params ONCE per block for the whole phase
    for (int i = tid; i < (HH * HH) / 4; i += 128) {
        int k = i >> 4, j = i & 15;
        int slot = ((j & 1) << 3) | (j >> 1);
        ((float4*)wsm)[k * 16 + slot] = ((const float4*)W)[i];
    }
    if (tid < HH) { gsm[tid] = g[tid]; besm[tid] = be[tid]; }
    __syncthreads();

    for (int t = blockIdx.x; t < BB * 16; t += gridDim.x) {
        __syncthreads();              // hsm free from previous tile
        int b = t >> 4;
        int pbase = (t & 15) << 7;
        int p0 = pbase + pg * 8;
        const float* hbase = hin + ((size_t)b * HH) * NN + pbase;
#pragma unroll
        for (int it = 0; it < 16; it++) {
            int i = it * 128 + tid;
            int r = i >> 5, c4 = i & 31;
            cp_async_cg16(hsm_base + (r * 128 + c4 * 4) * 4,
                          hbase + (size_t)r * NN + c4 * 4);
        }
        cp_commit();

        int sj[8];
        {
            int4 c0 = __ldcg((const int4*)(d_cs + b * NN + p0));
            int4 c1 = __ldcg((const int4*)(d_cs + b * NN + p0) + 1);
            sj[0] = c0.x; sj[1] = c0.y; sj[2] = c0.z; sj[3] = c0.w;
            sj[4] = c1.x; sj[5] = c1.y; sj[6] = c1.z; sj[7] = c1.w;
        }
        u64 acc2[8][4];
#pragma unroll
        for (int j = 0; j < 8; j++) {
            const float4* aw = (const float4*)(d_aggW + (((size_t)b * SS + sj[j]) << 6) + cg * 8);
            float4 a0 = __ldcg(aw), a1 = __ldcg(aw + 1);
            acc2[j][0] = pack2f(a0.x, a0.y);
            acc2[j][1] = pack2f(a0.z, a0.w);
            acc2[j][2] = pack2f(a1.x, a1.y);
            acc2[j][3] = pack2f(a1.z, a1.w);
        }

        cp_wait<0>();
        __syncthreads();

        for (int kc = 0; kc < 4; kc++) {
#pragma unroll
            for (int r = 0; r < 16; r++) {
                int k = kc * 16 + r;
                const float4* hp4 = (const float4*)(hsm + k * 128 + pg * 8);
                float4 hA = hp4[0], hB = hp4[1];
                const ulonglong2* wrow = (const ulonglong2*)(wsm + k * HH);
                ulonglong2 wv0 = wrow[cg];
                ulonglong2 wv1 = wrow[8 + cg];
                float hv[8] = {hA.x, hA.y, hA.z, hA.w, hB.x, hB.y, hB.z, hB.w};
#pragma unroll
                for (int j = 0; j < 8; j++) {
                    u64 hs = pack2f(hv[j], hv[j]);
                    acc2[j][0] = fma2f(hs, wv0.x, acc2[j][0]);
                    acc2[j][1] = fma2f(hs, wv0.y, acc2[j][1]);
                    acc2[j][2] = fma2f(hs, wv1.x, acc2[j][2]);
                    acc2[j][3] = fma2f(hs, wv1.y, acc2[j][3]);
                }
            }
        }

        float acc[8][8];
#pragma unroll
        for (int j = 0; j < 8; j++)
#pragma unroll
            for (int i = 0; i < 4; i++) unpack2f(acc2[j][i], acc[j][2 * i], acc[j][2 * i + 1]);

        const unsigned fm = 0xffffffffu;
        float s1[8];
#pragma unroll
        for (int j = 0; j < 8; j++) {
            float tt = 0.f;
#pragma unroll
            for (int i = 0; i < 8; i++) tt += acc[j][i];
            s1[j] = tt;
        }
#pragma unroll
        for (int d = 1; d < 8; d <<= 1)
#pragma unroll
            for (int j = 0; j < 8; j++) s1[j] += __shfl_xor_sync(fm, s1[j], d);
        float mu[8];
#pragma unroll
        for (int j = 0; j < 8; j++) mu[j] = s1[j] * (1.0f / 64.0f);
        float s2[8];
#pragma unroll
        for (int j = 0; j < 8; j++) {
            float tt = 0.f;
#pragma unroll
            for (int i = 0; i < 8; i++) { float d = acc[j][i] - mu[j]; tt = fmaf(d, d, tt); }
            s2[j] = tt;
        }
#pragma unroll
        for (int d = 1; d < 8; d <<= 1)
#pragma unroll
            for (int j = 0; j < 8; j++) s2[j] += __shfl_xor_sync(fm, s2[j], d);
        float rs[8];
#pragma unroll
        for (int j = 0; j < 8; j++) rs[j] = rsqrtf(s2[j] * (1.0f / 64.0f) + 1e-5f);

#pragma unroll
        for (int j = 0; j < 8; j++)
#pragma unroll
            for (int i = 0; i < 8; i++) {
                int c = cg * 8 + i;
                acc[j][i] = fmaxf(fmaf((acc[j][i] - mu[j]) * rs[j], gsm[c], besm[c]), 0.0f);
            }

        if (WRITE) {
            float* hp = hout + ((size_t)b * HH) * NN + p0;
#pragma unroll
            for (int i = 0; i < 8; i++) {
                int c = cg * 8 + i;
                float4 v0 = make_float4(acc[0][i], acc[1][i], acc[2][i], acc[3][i]);
                float4 v1 = make_float4(acc[4][i], acc[5][i], acc[6][i], acc[7][i]);
                __stcg((float4*)(hp + (size_t)c * NN), v0);
                __stcg((float4*)(hp + (size_t)c * NN + 4), v1);
            }
        }

        float* agg = aggdst + ((size_t)b << 12);
        float run[8];
#pragma unroll
        for (int i = 0; i < 8; i++) run[i] = acc[0][i];
        int sprev = sj[0];
#pragma unroll
        for (int j = 1; j < 8; j++) {
            if (sj[j] == sprev) {
#pragma unroll
                for (int i = 0; i < 8; i++) run[i] = fmaxf(run[i], acc[j][i]);
            } else {
                float* dst = agg + (sprev << 6) + cg * 8;
#pragma unroll
                for (int i = 0; i < 8; i++) atomicMax((int*)(dst + i), __float_as_int(run[i]));
                sprev = sj[j];
#pragma unroll
                for (int i = 0; i < 8; i++) run[i] = acc[j][i];
            }
        }
        float* dst = agg + (sprev << 6) + cg * 8;
#pragma unroll
        for (int i = 0; i < 8; i++) atomicMax((int*)(dst + i), __float_as_int(run[i]));
    }
}

// ---------------- the whole pipeline, one persistent kernel ----------------
__global__ __launch_bounds__(128) void fused_kernel(
    const float* __restrict__ x, const void* __restrict__ cl,
    const float* __restrict__ W0, const float* __restrict__ b0,
    const float* __restrict__ g0, const float* __restrict__ e0,
    const float* __restrict__ W1, const float* __restrict__ b1,
    const float* __restrict__ g1, const float* __restrict__ e1,
    const float* __restrict__ W2, const float* __restrict__ b2,
    const float* __restrict__ g2, const float* __restrict__ e2,
    float* __restrict__ out) {
    extern __shared__ __align__(16) float sm[];
    int tid = threadIdx.x, bid = blockIdx.x, nb = gridDim.x;

    // ---- P0: dtype detect + counting sort + zero aggs (batch-per-block, grid-stride) ----
    {
        int* cnt  = (int*)sm;
        int* cur  = cnt + SS;
        int* isll = cur + SS;
        const long long* p64 = (const long long*)cl;
        const int*       p32 = (const int*)cl;
        for (int b = bid; b < BB; b += nb) {
            __syncthreads();
            if (tid == 0) {
                int ok = 1;
                for (int i = 0; i < 16; i++) { long long v = p64[i]; if (v < 0 || v >= SS) ok = 0; }
                *isll = ok;
            }
            if (tid < SS) cnt[tid] = 0;
            for (int i = tid; i < SS * HH; i += 128) {
                __stcg(d_agg0 + b * SS * HH + i, 0.f);
                __stcg(d_agg1 + b * SS * HH + i, 0.f);
                __stcg(d_agg2 + b * SS * HH + i, 0.f);
            }
            __syncthreads();
            int l = *isll;
            for (int n = tid; n < NN; n += 128) {
                int s = l ? (int)p64[(size_t)b * NN + n] : p32[(size_t)b * NN + n];
                atomicAdd(&cnt[s], 1);
            }
            __syncthreads();
            if (tid == 0) {
                int run = 0;
                for (int s = 0; s < SS; s++) { int c = cnt[s]; cur[s] = run; run += c; }
            }
            __syncthreads();
            for (int n = tid; n < NN; n += 128) {
                int s = l ? (int)p64[(size_t)b * NN + n] : p32[(size_t)b * NN + n];
                int r = atomicAdd(&cur[s], 1);
                __stcg(d_perm + b * NN + r, n);
                __stcg(d_cs + b * NN + r, s);
            }
        }
    }
    gbar(0);

    // ---- P1: layer 0 (1 point/thread, grid-stride over 2048 tiles of 128 pts) ----
    {
        float* Wsm  = sm;            // 8x64
        float* bsm  = sm + 8 * HH;
        float* gsm  = bsm + HH;
        float* besm = gsm + HH;
        for (int i = tid; i < 8 * HH; i += 128) Wsm[i] = W0[i];
        if (tid < HH) { bsm[tid] = b0[tid]; gsm[tid] = g0[tid]; besm[tid] = e0[tid]; }
        __syncthreads();
        for (int t = bid; t < BB * 16; t += nb) {
            int b = t >> 4;
            int rank = ((t & 15) << 7) + tid;
            int n = __ldcg(d_perm + b * NN + rank);
            int s = __ldcg(d_cs + b * NN + rank);
            const float4* xp = (const float4*)(x + ((size_t)b * NN + n) * 8);
            float4 xa = xp[0], xb = xp[1];
            float xv[8] = {xa.x, xa.y, xa.z, xa.w, xb.x, xb.y, xb.z, xb.w};
            float acc[HH];
#pragma unroll
            for (int i = 0; i < HH; i++) acc[i] = bsm[i];
#pragma unroll
            for (int k = 0; k < 8; k++) {
                float h = xv[k];
                const float* wr = Wsm + k * HH;
#pragma unroll
                for (int i = 0; i < HH; i++) acc[i] = fmaf(h, wr[i], acc[i]);
            }
            float sum = 0.f;
#pragma unroll
            for (int i = 0; i < HH; i++) sum += acc[i];
            float mu = sum * (1.0f / 64.0f);
            float ssq = 0.f;
#pragma unroll
            for (int i = 0; i < HH; i++) { float d = acc[i] - mu; ssq = fmaf(d, d, ssq); }
            float rsv = rsqrtf(ssq * (1.0f / 64.0f) + 1e-5f);
            float* houtp = d_h0 + ((size_t)b * HH) * NN + rank;
#pragma unroll
            for (int i = 0; i < HH; i++) {
                float r = fmaxf(fmaf((acc[i] - mu) * rsv, gsm[i], besm[i]), 0.0f);
                __stcg(houtp + (size_t)i * NN, r);
                acc[i] = r;
            }
            unsigned match = __match_any_sync(0xffffffffu, s);
            bool leader = ((tid & 31) == (__ffs(match) - 1));
            float* agg = d_agg0 + (((b << 6) + s) << 6);
#pragma unroll
            for (int i = 0; i < HH; i++) {
                int m = __reduce_max_sync(match, __float_as_int(acc[i]));
                if (leader) atomicMax((int*)(agg + i), m);
            }
        }
    }
    gbar(1);

    smallmm_phase(sm, W1, b1, d_agg0);
    gbar(2);

    layer12_phase<true>(sm, W1, g1, e1, d_h0, d_h1, d_agg1);
    gbar(3);

    smallmm_phase(sm, W2, b2, d_agg1);
    gbar(4);

    layer12_phase<false>(sm, W2, g2, e2, d_h1, (float*)0, d_agg2);
    gbar(5);

    // ---- P6: normalize + write out (both halves identical) ----
    {
        int stride = nb * 128;
        for (int gid = bid * 128 + tid; gid < BB * HH; gid += stride) {
            int b = gid >> 6, c = gid & 63;
            const float* a = d_agg2 + b * SS * HH;
            float ssn = 0.f;
#pragma unroll 8
            for (int s = 0; s < SS; s++) { float v = __ldcg(a + s * HH + c); ssn = fmaf(v, v, ssn); }
            float inv = 1.0f / fmaxf(sqrtf(ssn), 1e-12f);
            for (int s = 0; s < SS; s++) {
                float o = __ldcg(a + s * HH + c) * inv;
                float* op = out + ((size_t)(b * SS + s)) * 128;
                op[c]      = o;
                op[64 + c] = o;
            }
        }
    }
}

// ---------------- launch ----------------
extern "C" void kernel_launch(void* const* d_in, const int* in_sizes, int n_in,
                              void* d_out, int out_size) {
    const float* x  = (const float*)d_in[0];
    const void*  cl = d_in[1];
    const float* W0 = (const float*)d_in[2];
    const float* b0 = (const float*)d_in[3];
    const float* g0 = (const float*)d_in[4];
    const float* e0 = (const float*)d_in[5];
    const float* W1 = (const float*)d_in[6];
    const float* b1 = (const float*)d_in[7];
    const float* g1 = (const float*)d_in[8];
    const float* e1 = (const float*)d_in[9];
    const float* W2 = (const float*)d_in[10];
    const float* b2 = (const float*)d_in[11];
    const float* g2 = (const float*)d_in[12];
    const float* e2 = (const float*)d_in[13];
    float* out = (float*)d_out;

    static int grid = 0;
    if (grid == 0) {
        cudaFuncSetAttribute(fused_kernel, cudaFuncAttributeMaxDynamicSharedMemorySize, FK_SMEM);
        int dev = 0;
        cudaGetDevice(&dev);
        int nsm = 0;
        cudaDeviceGetAttribute(&nsm, cudaDevAttrMultiProcessorCount, dev);
        int occ = 0;
        cudaOccupancyMaxActiveBlocksPerMultiprocessor(&occ, fused_kernel, 128, FK_SMEM);
        if (occ < 1) occ = 1;
        if (nsm < 1) nsm = 1;
        grid = nsm * occ;            // guaranteed co-resident -> barrier cannot deadlock
    }
    fused_kernel<<<grid, 128, FK_SMEM>>>(x, cl, W0, b0, g0, e0,
                                         W1, b1, g1, e1, W2, b2, g2, e2, out);
}

// round 14
// speedup vs baseline: 1.6426x; 1.6426x over previous
#include <cuda_runtime.h>
#include <cstdint>
#include <cstddef>

#define BB 128
#define NN 2048
#define HH 64
#define SS 64

typedef unsigned long long u64;

// ---------------- scratch (static device memory; no allocation) ----------------
__device__ __align__(256) float d_h0[(size_t)BB * HH * NN];   // 64 MB, [b][c][rank]
__device__ __align__(256) float d_h1[(size_t)BB * HH * NN];   // 64 MB
__device__ __align__(256) float d_agg0[BB * SS * HH];
__device__ __align__(256) float d_agg1[BB * SS * HH];
__device__ __align__(256) float d_agg2[BB * SS * HH];
__device__ __align__(256) float d_aggW[BB * SS * HH];         // bias + agg@W_bot, per layer
__device__ int            d_perm[BB * NN];
__device__ int            d_cs[BB * NN];                      // sorted cluster ids

// ---------------- f32x2 packed fp32 helpers (bit-exact IEEE fma on both halves) ----------------
__device__ __forceinline__ u64 pack2f(float lo, float hi) {
    u64 r; asm("mov.b64 %0, {%1,%2};" : "=l"(r) : "f"(lo), "f"(hi)); return r;
}
__device__ __forceinline__ void unpack2f(u64 v, float& lo, float& hi) {
    asm("mov.b64 {%0,%1}, %2;" : "=f"(lo), "=f"(hi) : "l"(v));
}
__device__ __forceinline__ u64 fma2f(u64 a, u64 b, u64 c) {
    u64 d; asm("fma.rn.f32x2 %0, %1, %2, %3;" : "=l"(d) : "l"(a), "l"(b), "l"(c)); return d;
}

// ---------------- cp.async helpers ----------------
__device__ __forceinline__ void cp_async16(uint32_t dst_smem, const void* src) {
    asm volatile("cp.async.ca.shared.global [%0], [%1], 16;" :: "r"(dst_smem), "l"(src));
}
__device__ __forceinline__ void cp_commit() {
    asm volatile("cp.async.commit_group;" ::: "memory");
}
template <int N>
__device__ __forceinline__ void cp_wait() {
    asm volatile("cp.async.wait_group %0;" :: "n"(N) : "memory");
}

// ---------------- PDL: programmatic dependent launch ----------------
// wait: block until predecessor grid's pre-trigger writes are visible.
// trigger: allow dependent grid to launch (fires when all blocks execute it).
__device__ __forceinline__ void pdl_wait()    { asm volatile("griddepcontrol.wait;" ::: "memory"); }
__device__ __forceinline__ void pdl_trigger() { asm volatile("griddepcontrol.launch_dependents;" ::: "memory"); }

// ---------------- prep: dtype-detect + per-batch counting sort + agg zero ----------------
__global__ void prep_kernel(const void* __restrict__ cl) {
    __shared__ int cnt[SS];
    __shared__ int cur[SS];
    __shared__ int isll;
    int b = blockIdx.x, tid = threadIdx.x;
    pdl_wait();   // first kernel in chain; wait is cheap and keeps semantics uniform
    if (tid == 0) {
        const long long* p = (const long long*)cl;
        int ok = 1;
        for (int i = 0; i < 16; i++) { long long v = p[i]; if (v < 0 || v >= SS) ok = 0; }
        isll = ok;
    }
    if (tid < SS) cnt[tid] = 0;
    float* a0 = d_agg0 + b * SS * HH;
    float* a1 = d_agg1 + b * SS * HH;
    float* a2 = d_agg2 + b * SS * HH;
    for (int i = tid; i < SS * HH; i += blockDim.x) { a0[i] = 0.f; a1[i] = 0.f; a2[i] = 0.f; }
    __syncthreads();
    const long long* p64 = (const long long*)cl;
    const int*       p32 = (const int*)cl;
    int l = isll;
    for (int n = tid; n < NN; n += blockDim.x) {
        int s = l ? (int)p64[(size_t)b * NN + n] : p32[(size_t)b * NN + n];
        atomicAdd(&cnt[s], 1);
    }
    __syncthreads();
    if (tid == 0) {
        int run = 0;
        for (int s = 0; s < SS; s++) { int c = cnt[s]; cur[s] = run; run += c; }
    }
    __syncthreads();
    for (int n = tid; n < NN; n += blockDim.x) {
        int s = l ? (int)p64[(size_t)b * NN + n] : p32[(size_t)b * NN + n];
        int r = atomicAdd(&cur[s], 1);
        d_perm[b * NN + r] = n;
        d_cs[b * NN + r]   = s;
    }
    pdl_trigger();
}

// ---------------- layer 0: gather x via perm, 8->64 matvec, LN/relu, write h0 + agg0 ----------------
__global__ __launch_bounds__(256) void layer0_kernel(const float* __restrict__ x,
                                                     const float* __restrict__ W0,
                                                     const float* __restrict__ b0,
                                                     const float* __restrict__ g0,
                                                     const float* __restrict__ be0) {
    __shared__ __align__(16) float Wsm[8 * HH];
    __shared__ float bsm[HH], gsm[HH], besm[HH];
    int tid = threadIdx.x, b = blockIdx.y;
    int rank = blockIdx.x * 256 + tid;
    // stage inputs (not produced by predecessor) BEFORE waiting -> overlaps prep's tail
    for (int i = tid; i < 8 * HH; i += 256) Wsm[i] = W0[i];
    if (tid < HH) { bsm[tid] = b0[tid]; gsm[tid] = g0[tid]; besm[tid] = be0[tid]; }
    __syncthreads();
    pdl_wait();
    int n = d_perm[b * NN + rank];
    int s = d_cs[b * NN + rank];
    const float4* xp = (const float4*)(x + ((size_t)b * NN + n) * 8);
    float4 xa = xp[0], xb = xp[1];
    float xv[8] = {xa.x, xa.y, xa.z, xa.w, xb.x, xb.y, xb.z, xb.w};
    float acc[HH];
#pragma unroll
    for (int i = 0; i < HH; i++) acc[i] = bsm[i];
#pragma unroll
    for (int k = 0; k < 8; k++) {
        float h = xv[k];
        const float* wr = Wsm + k * HH;
#pragma unroll
        for (int i = 0; i < HH; i++) acc[i] = fmaf(h, wr[i], acc[i]);
    }
    float sum = 0.f;
#pragma unroll
    for (int i = 0; i < HH; i++) sum += acc[i];
    float mu = sum * (1.0f / 64.0f);
    float ssq = 0.f;
#pragma unroll
    for (int i = 0; i < HH; i++) { float d = acc[i] - mu; ssq = fmaf(d, d, ssq); }
    float rs = rsqrtf(ssq * (1.0f / 64.0f) + 1e-5f);
    float* houtp = d_h0 + ((size_t)b * HH) * NN + rank;
#pragma unroll
    for (int i = 0; i < HH; i++) {
        float r = fmaxf(fmaf((acc[i] - mu) * rs, gsm[i], besm[i]), 0.0f);
        houtp[(size_t)i * NN] = r;
        acc[i] = r;
    }
    unsigned match = __match_any_sync(0xffffffffu, s);
    bool leader = ((threadIdx.x & 31) == (__ffs(match) - 1));
    float* agg = d_agg0 + (((b << 6) + s) << 6);
#pragma unroll
    for (int i = 0; i < HH; i++) {
        int m = __reduce_max_sync(match, __float_as_int(acc[i]));
        if (leader) atomicMax((int*)(agg + i), m);
    }
    pdl_trigger();
}

// ---------------- tiny GEMM: aggW[b] = bias + agg[b] @ W_bot (thread-per-output) ----------------
__global__ __launch_bounds__(256) void smallmm_kernel(const float* __restrict__ Wfull,
                                                      const float* __restrict__ bias, int stage) {
    __shared__ float Wsm[HH * HH];
    __shared__ float bsm[HH];
    const float* Wbot = Wfull + 64 * HH;
    const float* agg = (stage == 0) ? d_agg0 : d_agg1;
    int tid = threadIdx.x;
    int gid = blockIdx.x * 256 + tid;
    for (int i = tid; i < HH * HH; i += 256) Wsm[i] = Wbot[i];
    if (tid < HH) bsm[tid] = bias[tid];
    __syncthreads();
    pdl_wait();
    int c = gid & 63;
    int row = gid >> 6;
    const float* A = agg + (row << 6);
    float a = bsm[c];
#pragma unroll 8
    for (int k = 0; k < HH; k++) a = fmaf(A[k], Wsm[(k << 6) + c], a);
    d_aggW[gid] = a;
    pdl_trigger();
}

// ---------------- layers 1/2: P=8 x C=8 register-blocked GEMM, whole-tile h in smem ----
// block 128 threads = 16 point-groups x 8 channel-groups; tile = 128 points x 64 channels.
// W + params staged BEFORE pdl_wait (inputs); h cp.async + aggW/cs reads after.
// smem is DYNAMIC (49.7 KB > 48 KB static limit): [wsm 16K][hsm 32K][gsm 256][besm 256]
#define L12_SMEM ((HH * HH + HH * 128 + HH + HH) * 4)

template <int STAGE>
__global__ __launch_bounds__(128, 4) void layer12_kernel(const float* __restrict__ W,
                                                         const float* __restrict__ g,
                                                         const float* __restrict__ be) {
    extern __shared__ __align__(16) float smem_dyn[];
    float* wsm  = smem_dyn;                    // 16 KB, swizzled [k][slot]
    float* hsm  = smem_dyn + HH * HH;          // 32 KB, [k][point]
    float* gsm  = hsm + HH * 128;              // 256 B
    float* besm = gsm + HH;                    // 256 B
    int tid = threadIdx.x, b = blockIdx.y;
    int pg = tid >> 3;          // 0..15
    int cg = tid & 7;           // 0..7
    int pbase = blockIdx.x * 128;
    int p0 = pbase + pg * 8;    // first of this thread's 8 points

    // stage W with swizzle (float4 j of row k at slot ((j&1)<<3)|(j>>1)) — input, pre-wait
    for (int i = tid; i < (HH * HH) / 4; i += 128) {
        int k = i >> 4, j = i & 15;
        int slot = ((j & 1) << 3) | (j >> 1);
        ((float4*)wsm)[k * 16 + slot] = ((const float4*)W)[i];
    }
    if (tid < HH) { gsm[tid] = g[tid]; besm[tid] = be[tid]; }

    pdl_wait();

    // full h tile cp.async (predecessor output)
    const float* hbase = ((STAGE == 1) ? d_h0 : d_h1) + ((size_t)b * HH) * NN + pbase;
    uint32_t hsm_base = (uint32_t)__cvta_generic_to_shared(hsm);
#pragma unroll
    for (int it = 0; it < 16; it++) {
        int i = it * 128 + tid;           // 0..2047 float4s
        int r = i >> 5, c4 = i & 31;
        cp_async16(hsm_base + (r * 128 + c4 * 4) * 4,
                   hbase + (size_t)r * NN + c4 * 4);
    }
    cp_commit();

    // per-point cluster ids (8 consecutive ints = 2 int4)
    int sj[8];
    {
        const int4* cp = (const int4*)(d_cs + b * NN + p0);
        int4 c0 = cp[0], c1 = cp[1];
        sj[0] = c0.x; sj[1] = c0.y; sj[2] = c0.z; sj[3] = c0.w;
        sj[4] = c1.x; sj[5] = c1.y; sj[6] = c1.z; sj[7] = c1.w;
    }
    // acc init from aggW[s] (bias folded in)
    u64 acc2[8][4];
#pragma unroll
    for (int j = 0; j < 8; j++) {
        const float4* aw = (const float4*)(d_aggW + (((size_t)b * SS + sj[j]) << 6) + cg * 8);
        float4 a0 = aw[0], a1 = aw[1];
        acc2[j][0] = pack2f(a0.x, a0.y);
        acc2[j][1] = pack2f(a0.z, a0.w);
        acc2[j][2] = pack2f(a1.x, a1.y);
        acc2[j][3] = pack2f(a1.z, a1.w);
    }

    cp_wait<0>();
    __syncthreads();

    // barrier-free mainloop: 64 k-iterations
    for (int kc = 0; kc < 4; kc++) {
#pragma unroll
        for (int r = 0; r < 16; r++) {
            int k = kc * 16 + r;
            const float4* hp4 = (const float4*)(hsm + k * 128 + pg * 8);
            float4 hA = hp4[0], hB = hp4[1];
            const ulonglong2* wrow = (const ulonglong2*)(wsm + k * HH);
            ulonglong2 wv0 = wrow[cg];        // channels 8cg..8cg+3
            ulonglong2 wv1 = wrow[8 + cg];    // channels 8cg+4..8cg+7
            float hv[8] = {hA.x, hA.y, hA.z, hA.w, hB.x, hB.y, hB.z, hB.w};
#pragma unroll
            for (int j = 0; j < 8; j++) {
                u64 hs = pack2f(hv[j], hv[j]);
                acc2[j][0] = fma2f(hs, wv0.x, acc2[j][0]);
                acc2[j][1] = fma2f(hs, wv0.y, acc2[j][1]);
                acc2[j][2] = fma2f(hs, wv1.x, acc2[j][2]);
                acc2[j][3] = fma2f(hs, wv1.y, acc2[j][3]);
            }
        }
    }

    float acc[8][8];
#pragma unroll
    for (int j = 0; j < 8; j++)
#pragma unroll
        for (int i = 0; i < 4; i++) unpack2f(acc2[j][i], acc[j][2 * i], acc[j][2 * i + 1]);

    // LN mean/var: butterfly over the 8 channel-group lanes (lane bits 0..2)
    const unsigned fm = 0xffffffffu;
    float s1[8];
#pragma unroll
    for (int j = 0; j < 8; j++) {
        float t = 0.f;
#pragma unroll
        for (int i = 0; i < 8; i++) t += acc[j][i];
        s1[j] = t;
    }
#pragma unroll
    for (int d = 1; d < 8; d <<= 1)
#pragma unroll
        for (int j = 0; j < 8; j++) s1[j] += __shfl_xor_sync(fm, s1[j], d);
    float mu[8];
#pragma unroll
    for (int j = 0; j < 8; j++) mu[j] = s1[j] * (1.0f / 64.0f);
    float s2[8];
#pragma unroll
    for (int j = 0; j < 8; j++) {
        float t = 0.f;
#pragma unroll
        for (int i = 0; i < 8; i++) { float d = acc[j][i] - mu[j]; t = fmaf(d, d, t); }
        s2[j] = t;
    }
#pragma unroll
    for (int d = 1; d < 8; d <<= 1)
#pragma unroll
        for (int j = 0; j < 8; j++) s2[j] += __shfl_xor_sync(fm, s2[j], d);
    float rs[8];
#pragma unroll
    for (int j = 0; j < 8; j++) rs[j] = rsqrtf(s2[j] * (1.0f / 64.0f) + 1e-5f);

    // normalize + relu
#pragma unroll
    for (int j = 0; j < 8; j++)
#pragma unroll
        for (int i = 0; i < 8; i++) {
            int c = cg * 8 + i;
            acc[j][i] = fmaxf(fmaf((acc[j][i] - mu[j]) * rs[j], gsm[c], besm[c]), 0.0f);
        }

    // write h (STAGE 1 only): two float4 per channel covering the 8 consecutive points
    if (STAGE == 1) {
        float* hout = d_h1 + ((size_t)b * HH) * NN + p0;
#pragma unroll
        for (int i = 0; i < 8; i++) {
            int c = cg * 8 + i;
            float4 v0 = make_float4(acc[0][i], acc[1][i], acc[2][i], acc[3][i]);
            float4 v1 = make_float4(acc[4][i], acc[5][i], acc[6][i], acc[7][i]);
            *(float4*)(hout + (size_t)c * NN)     = v0;
            *(float4*)(hout + (size_t)c * NN + 4) = v1;
        }
    }

    // segmented max over this thread's 8 consecutive (sorted) points: run-flush with atomics
    float* agg = ((STAGE == 1) ? d_agg1 : d_agg2) + ((size_t)b << 12);
    float run[8];
#pragma unroll
    for (int i = 0; i < 8; i++) run[i] = acc[0][i];
    int sprev = sj[0];
#pragma unroll
    for (int j = 1; j < 8; j++) {
        if (sj[j] == sprev) {
#pragma unroll
            for (int i = 0; i < 8; i++) run[i] = fmaxf(run[i], acc[j][i]);
        } else {
            float* dst = agg + (sprev << 6) + cg * 8;
#pragma unroll
            for (int i = 0; i < 8; i++) atomicMax((int*)(dst + i), __float_as_int(run[i]));
            sprev = sj[j];
#pragma unroll
            for (int i = 0; i < 8; i++) run[i] = acc[j][i];
        }
    }
    {
        float* dst = agg + (sprev << 6) + cg * 8;
#pragma unroll
        for (int i = 0; i < 8; i++) atomicMax((int*)(dst + i), __float_as_int(run[i]));
    }
    pdl_trigger();
}

// ---------------- final: out[b,s,c]=out[b,s,64+c]=agg2[b,s,c]/max(||col||, eps) ----------------
__global__ void final_kernel(float* __restrict__ out) {
    int b = blockIdx.x;
    int c = threadIdx.x;
    pdl_wait();
    const float* a = d_agg2 + b * SS * HH;
    float ss = 0.f;
#pragma unroll 8
    for (int s = 0; s < SS; s++) { float v = a[s * HH + c]; ss = fmaf(v, v, ss); }
    float inv = 1.0f / fmaxf(sqrtf(ss), 1e-12f);
    for (int s = 0; s < SS; s++) {
        float o = a[s * HH + c] * inv;
        out[((size_t)(b * SS + s)) * 128 + c]      = o;
        out[((size_t)(b * SS + s)) * 128 + 64 + c] = o;
    }
}

// ---------------- launch (all with PDL stream-serialization attribute) ----------------
template <typename F, typename... Args>
static void launch_pdl(F f, dim3 grid, dim3 block, size_t smem, Args... args) {
    cudaLaunchConfig_t cfg = {};
    cfg.gridDim = grid;
    cfg.blockDim = block;
    cfg.dynamicSmemBytes = smem;
    cfg.stream = 0;
    cudaLaunchAttribute attr[1];
    attr[0].id = cudaLaunchAttributeProgrammaticStreamSerialization;
    attr[0].val.programmaticStreamSerializationAllowed = 1;
    cfg.attrs = attr;
    cfg.numAttrs = 1;
    cudaLaunchKernelEx(&cfg, f, args...);
}

extern "C" void kernel_launch(void* const* d_in, const int* in_sizes, int n_in,
                              void* d_out, int out_size) {
    const float* x  = (const float*)d_in[0];
    const void*  cl = d_in[1];
    const float* W0 = (const float*)d_in[2];
    const float* b0 = (const float*)d_in[3];
    const float* g0 = (const float*)d_in[4];
    const float* e0 = (const float*)d_in[5];
    const float* W1 = (const float*)d_in[6];
    const float* b1 = (const float*)d_in[7];
    const float* g1 = (const float*)d_in[8];
    const float* e1 = (const float*)d_in[9];
    const float* W2 = (const float*)d_in[10];
    const float* b2 = (const float*)d_in[11];
    const float* g2 = (const float*)d_in[12];
    const float* e2 = (const float*)d_in[13];
    float* out = (float*)d_out;

    const int SMALLMM_BLOCKS = (BB * SS * HH) / 256;               // 2048

    cudaFuncSetAttribute(layer12_kernel<1>, cudaFuncAttributeMaxDynamicSharedMemorySize, L12_SMEM);
    cudaFuncSetAttribute(layer12_kernel<2>, cudaFuncAttributeMaxDynamicSharedMemorySize, L12_SMEM);

    launch_pdl(prep_kernel, dim3(BB), dim3(256), 0, cl);                              // 1
    launch_pdl(layer0_kernel, dim3(NN / 256, BB), dim3(256), 0, x, W0, b0, g0, e0);   // 2
    launch_pdl(smallmm_kernel, dim3(SMALLMM_BLOCKS), dim3(256), 0, W1, b1, 0);        // 3
    launch_pdl(layer12_kernel<1>, dim3(NN / 128, BB), dim3(128), (size_t)L12_SMEM,
               W1, g1, e1);                                                            // 4
    launch_pdl(smallmm_kernel, dim3(SMALLMM_BLOCKS), dim3(256), 0, W2, b2, 1);        // 5
    launch_pdl(layer12_kernel<2>, dim3(NN / 128, BB), dim3(128), (size_t)L12_SMEM,
               W2, g2, e2);                                                            // 6  <- ncu -s5 -c1
    launch_pdl(final_kernel, dim3(BB), dim3(64), 0, out);                             // 7
}